// round 3
// baseline (speedup 1.0000x reference)
#include <cuda_runtime.h>

#define HID   128
#define MAXN  100000
#define MAXE  1048576       // 2E upper bound
#define ZP    68            // padded z-tile row (float4-aligned, conflict-light)

// Scratch (static __device__ — allocation guards forbid cudaMalloc)
__device__ float g_A[MAXN * HID];     // 51.2 MB
__device__ float g_B[MAXN * HID];     // 51.2 MB
__device__ int   g_SIDX[MAXE];        // 4 MB
__device__ int   g_DIDX[MAXE];        // 4 MB
__device__ int   g_idx64;             // 1 if index arrays are int64

// ---------- packed f32x2 helpers (FFMA2 path; 2x fp32 FMA throughput) ----------
__device__ __forceinline__ unsigned long long pack2(float lo, float hi) {
    unsigned long long r;
    asm("mov.b64 %0, {%1, %2};" : "=l"(r) : "f"(lo), "f"(hi));
    return r;
}
__device__ __forceinline__ unsigned long long fma2(unsigned long long a,
                                                   unsigned long long b,
                                                   unsigned long long c) {
    unsigned long long d;
    asm("fma.rn.f32x2 %0, %1, %2, %3;" : "=l"(d) : "l"(a), "l"(b), "l"(c));
    return d;
}
__device__ __forceinline__ float2 unpack2(unsigned long long v) {
    float2 f;
    asm("mov.b64 {%0, %1}, %2;" : "=f"(f.x), "=f"(f.y) : "l"(v));
    return f;
}

// ---------------------------------------------------------------------------
// Detect whether index arrays are int64 or int32 (JAX x64-disabled trap).
// Sample entries interpreted as int64; any value outside [0, nNodes) => int32.
// Sample indices stay < E/2 so the read is in-bounds under either dtype.
// ---------------------------------------------------------------------------
__global__ void detect_kernel(const void* ps, const void* pd,
                              const void* ns, const void* nd,
                              int E, int nNodes)
{
    if (threadIdx.x != 0 || blockIdx.x != 0) return;
    const long long* arrs[4] = {(const long long*)ps, (const long long*)pd,
                                (const long long*)ns, (const long long*)nd};
    int step = (E / 2) / 8;
    if (step < 1) step = 1;
    int ok = 1;
    for (int a = 0; a < 4; a++)
        for (int j = 0; j < 8; j++) {
            long long v = arrs[a][(long long)j * step];
            if (v < 0 || v >= nNodes) ok = 0;
        }
    g_idx64 = ok;
}

// ---------------------------------------------------------------------------
// Normalize indices to int32 scratch, fusing the pos/neg concat. Clamped so
// the edge kernel can never fault even if detection were wrong.
// ---------------------------------------------------------------------------
__global__ void convert_idx_kernel(const void* ps, const void* pd,
                                   const void* ns, const void* nd,
                                   int E2, int Eh, int nNodes)
{
    int i = blockIdx.x * blockDim.x + threadIdx.x;
    if (i >= E2) return;
    const int f64 = g_idx64;
    long long s, d;
    if (i < Eh) {
        s = f64 ? ((const long long*)ps)[i] : (long long)((const int*)ps)[i];
        d = f64 ? ((const long long*)pd)[i] : (long long)((const int*)pd)[i];
    } else {
        int j = i - Eh;
        s = f64 ? ((const long long*)ns)[j] : (long long)((const int*)ns)[j];
        d = f64 ? ((const long long*)nd)[j] : (long long)((const int*)nd)[j];
    }
    if (s < 0) s = 0; if (s >= nNodes) s = nNodes - 1;
    if (d < 0) d = 0; if (d >= nNodes) d = nNodes - 1;
    g_SIDX[i] = (int)s;
    g_DIDX[i] = (int)d;
}

// ---------------------------------------------------------------------------
// Precompute kernel: per node-tile of 64 nodes,
//   half==0: g_A[n] = z_src[n] @ W1[0:128]   + b1
//   half==1: g_B[n] = z_dst[n] @ W1[128:256]
// Block: 256 threads; each thread 4 nodes x 8 cols as f32x2 accumulators.
// ---------------------------------------------------------------------------
__global__ __launch_bounds__(256, 2) void precompute_kernel(
    const float* __restrict__ zsrc, const float* __restrict__ zdst,
    const float* __restrict__ W1, const float* __restrict__ b1, int nNodes)
{
    extern __shared__ float smem[];
    float* sW = smem;                 // [128][128]
    float* sZ = smem + HID * HID;     // [128][ZP]  (zT[k][node_local])

    const int half = blockIdx.y;
    const float* z   = half ? zdst : zsrc;
    float*       out = half ? g_B  : g_A;
    const float* Wh  = W1 + half * HID * HID;   // W1 row-major [256][128]

    {
        const float4* wv  = (const float4*)Wh;
        float4*       swv = (float4*)sW;
        for (int i = threadIdx.x; i < HID * HID / 4; i += 256) swv[i] = wv[i];
    }

    const int n0 = blockIdx.x * 64;
    {
        const int lane = threadIdx.x & 31;
        const int wrp  = threadIdx.x >> 5;
        for (int i = 0; i < 8; i++) {
            int nloc = wrp * 8 + i;
            int node = n0 + nloc;
            float4 v = make_float4(0.f, 0.f, 0.f, 0.f);
            if (node < nNodes)
                v = ((const float4*)(z + (size_t)node * HID))[lane];
            sZ[(lane * 4 + 0) * ZP + nloc] = v.x;
            sZ[(lane * 4 + 1) * ZP + nloc] = v.y;
            sZ[(lane * 4 + 2) * ZP + nloc] = v.z;
            sZ[(lane * 4 + 3) * ZP + nloc] = v.w;
        }
    }
    __syncthreads();

    const int ng = threadIdx.x & 15;   // node group: nodes ng*4 .. ng*4+3
    const int cg = threadIdx.x >> 4;   // col group : cols  cg*8 .. cg*8+7

    unsigned long long acc[4][4];
    {
        unsigned long long init[4];
        #pragma unroll
        for (int j = 0; j < 4; j++)
            init[j] = (half == 0)
                    ? pack2(b1[cg * 8 + j * 2], b1[cg * 8 + j * 2 + 1])
                    : 0ULL;
        #pragma unroll
        for (int i = 0; i < 4; i++)
            #pragma unroll
            for (int j = 0; j < 4; j++) acc[i][j] = init[j];
    }

    #pragma unroll 4
    for (int k = 0; k < HID; k++) {
        float4 zv = *(const float4*)&sZ[k * ZP + ng * 4];
        float4 w0 = *(const float4*)&sW[k * HID + cg * 8];
        float4 w1 = *(const float4*)&sW[k * HID + cg * 8 + 4];
        unsigned long long wp[4];
        wp[0] = pack2(w0.x, w0.y);
        wp[1] = pack2(w0.z, w0.w);
        wp[2] = pack2(w1.x, w1.y);
        wp[3] = pack2(w1.z, w1.w);
        float zz[4] = {zv.x, zv.y, zv.z, zv.w};
        #pragma unroll
        for (int i = 0; i < 4; i++) {
            unsigned long long zpk = pack2(zz[i], zz[i]);
            #pragma unroll
            for (int j = 0; j < 4; j++)
                acc[i][j] = fma2(zpk, wp[j], acc[i][j]);
        }
    }

    #pragma unroll
    for (int i = 0; i < 4; i++) {
        int node = n0 + ng * 4 + i;
        if (node >= nNodes) continue;
        float2 p0 = unpack2(acc[i][0]);
        float2 p1 = unpack2(acc[i][1]);
        float2 p2 = unpack2(acc[i][2]);
        float2 p3 = unpack2(acc[i][3]);
        float4* op = (float4*)(out + (size_t)node * HID + cg * 8);
        op[0] = make_float4(p0.x, p0.y, p1.x, p1.y);
        op[1] = make_float4(p2.x, p2.y, p3.x, p3.y);
    }
}

// ---------------------------------------------------------------------------
// Edge kernel: one warp per edge.  out[e] = relu(A[s]+B[d]) . W2 + b2
// Lane l holds cols 4l..4l+3 (float4) -> two coalesced 512B row gathers.
// ---------------------------------------------------------------------------
__global__ __launch_bounds__(256) void edge_kernel(
    const float* __restrict__ W2, const float* __restrict__ b2,
    float* __restrict__ out, int E2)
{
    const int lane = threadIdx.x & 31;
    const int gw   = (blockIdx.x * blockDim.x + threadIdx.x) >> 5;
    const int nw   = (gridDim.x * blockDim.x) >> 5;

    const float4 w2v = ((const float4*)W2)[lane];
    const float  b2s = b2[0];
    const float4* A4 = (const float4*)g_A;
    const float4* B4 = (const float4*)g_B;

    for (int e = gw; e < E2; e += nw) {
        size_t s = (size_t)g_SIDX[e];
        size_t d = (size_t)g_DIDX[e];

        float4 a = A4[s * 32 + lane];
        float4 b = B4[d * 32 + lane];

        float hx = fmaxf(a.x + b.x, 0.f);
        float hy = fmaxf(a.y + b.y, 0.f);
        float hz = fmaxf(a.z + b.z, 0.f);
        float hw = fmaxf(a.w + b.w, 0.f);

        float p = hx * w2v.x + hy * w2v.y + hz * w2v.z + hw * w2v.w;
        #pragma unroll
        for (int off = 16; off; off >>= 1)
            p += __shfl_xor_sync(0xffffffffu, p, off);

        if (lane == 0) out[e] = p + b2s;
    }
}

// ---------------------------------------------------------------------------
extern "C" void kernel_launch(void* const* d_in, const int* in_sizes, int n_in,
                              void* d_out, int out_size)
{
    // Resolve input ordering: dict order vs name-sorted order.
    const float *zsrc, *zdst, *W1, *b1, *W2, *b2;
    const void  *ps, *pd, *ns, *nd;
    int zElems, eElems;
    if (in_sizes[0] == 2 * HID * HID) {
        // name-sorted: W1, W2, b1, b2, neg_dst, neg_src, pos_dst, pos_src, z_dst, z_src
        W1 = (const float*)d_in[0];
        W2 = (const float*)d_in[1];
        b1 = (const float*)d_in[2];
        b2 = (const float*)d_in[3];
        nd = d_in[4]; ns = d_in[5];
        pd = d_in[6]; ps = d_in[7];
        zdst = (const float*)d_in[8];
        zsrc = (const float*)d_in[9];
        zElems = in_sizes[8];
        eElems = in_sizes[4];
    } else {
        // dict order: z_src, z_dst, pos_src, pos_dst, neg_src, neg_dst, W1, b1, W2, b2
        zsrc = (const float*)d_in[0];
        zdst = (const float*)d_in[1];
        ps = d_in[2]; pd = d_in[3];
        ns = d_in[4]; nd = d_in[5];
        W1 = (const float*)d_in[6];
        b1 = (const float*)d_in[7];
        W2 = (const float*)d_in[8];
        b2 = (const float*)d_in[9];
        zElems = in_sizes[0];
        eElems = in_sizes[2];
    }

    int nNodes = zElems / HID;
    if (nNodes > MAXN) nNodes = MAXN;
    const int E2 = out_size;   // 2E
    const int Eh = eElems;     // E

    const int smem = (HID * HID + HID * ZP) * (int)sizeof(float);  // 100352 B
    cudaFuncSetAttribute(precompute_kernel,
                         cudaFuncAttributeMaxDynamicSharedMemorySize, smem);

    detect_kernel<<<1, 32>>>(ps, pd, ns, nd, Eh, nNodes);
    convert_idx_kernel<<<(E2 + 255) / 256, 256>>>(ps, pd, ns, nd, E2, Eh, nNodes);

    dim3 pgrid((nNodes + 63) / 64, 2);
    precompute_kernel<<<pgrid, 256, smem>>>(zsrc, zdst, W1, b1, nNodes);

    edge_kernel<<<8192, 256>>>(W2, b2, (float*)d_out, E2);
}

// round 4
// speedup vs baseline: 1.4187x; 1.4187x over previous
#include <cuda_runtime.h>

#define HID   128
#define MAXN  100000
#define MAXE  1048576

// Scratch (static __device__ — allocation guards forbid cudaMalloc)
__device__ float g_A[MAXN * HID];     // 51.2 MB
__device__ float g_B[MAXN * HID];     // 51.2 MB
__device__ int   g_SIDX[MAXE];        // 4 MB
__device__ int   g_DIDX[MAXE];        // 4 MB

// ---------- packed f32x2 helpers ----------
__device__ __forceinline__ unsigned long long pack2(float lo, float hi) {
    unsigned long long r;
    asm("mov.b64 %0, {%1, %2};" : "=l"(r) : "f"(lo), "f"(hi));
    return r;
}
__device__ __forceinline__ unsigned long long fma2(unsigned long long a,
                                                   unsigned long long b,
                                                   unsigned long long c) {
    unsigned long long d;
    asm("fma.rn.f32x2 %0, %1, %2, %3;" : "=l"(d) : "l"(a), "l"(b), "l"(c));
    return d;
}
__device__ __forceinline__ float2 unpack2(unsigned long long v) {
    float2 f;
    asm("mov.b64 {%0, %1}, %2;" : "=f"(f.x), "=f"(f.y) : "l"(v));
    return f;
}

// ---------------------------------------------------------------------------
// Index normalize (int64-vs-int32 detection fused in; per-block redetection
// hits cached lines so it's ~free). Output: int32, concat'd pos|neg, clamped.
// ---------------------------------------------------------------------------
__global__ void convert_idx_kernel(const void* ps, const void* pd,
                                   const void* ns, const void* nd,
                                   int E2, int Eh, int nNodes)
{
    __shared__ int sF64;
    if (threadIdx.x == 0) {
        const long long* arrs[4] = {(const long long*)ps, (const long long*)pd,
                                    (const long long*)ns, (const long long*)nd};
        int step = (Eh / 2) / 8;
        if (step < 1) step = 1;
        int ok = 1;
        for (int a = 0; a < 4; a++)
            for (int j = 0; j < 8; j++) {
                long long v = arrs[a][(long long)j * step];
                if (v < 0 || v >= nNodes) ok = 0;
            }
        sF64 = ok;
    }
    __syncthreads();
    const int f64 = sF64;

    int i = blockIdx.x * blockDim.x + threadIdx.x;
    if (i >= E2) return;
    long long s, d;
    if (i < Eh) {
        s = f64 ? ((const long long*)ps)[i] : (long long)((const int*)ps)[i];
        d = f64 ? ((const long long*)pd)[i] : (long long)((const int*)pd)[i];
    } else {
        int j = i - Eh;
        s = f64 ? ((const long long*)ns)[j] : (long long)((const int*)ns)[j];
        d = f64 ? ((const long long*)nd)[j] : (long long)((const int*)nd)[j];
    }
    if (s < 0) s = 0; if (s >= nNodes) s = nNodes - 1;
    if (d < 0) d = 0; if (d >= nNodes) d = nNodes - 1;
    g_SIDX[i] = (int)s;
    g_DIDX[i] = (int)d;
}

// ---------------------------------------------------------------------------
// Precompute (persistent CTAs):
//   half 0: g_A[n] = z_src[n] @ W1[0:128]   + b1
//   half 1: g_B[n] = z_dst[n] @ W1[128:256]
// Block 256 thr, 1 CTA/SM (131 KB smem). W loaded ONCE per CTA. z-tile (64
// nodes) register-prefetched, stored into shared PRE-DUPLICATED as {z,z} u64
// so the mainloop has ZERO pack MOVs: per k per thread = 8x LDS.64 + 16 FFMA2.
// Thread tile: 4 nodes (ng + 16i) x 8 cols (cg*8..+7 as 4 f32x2 pairs).
// ---------------------------------------------------------------------------
__global__ __launch_bounds__(256, 1) void precompute_kernel(
    const float* __restrict__ zsrc, const float* __restrict__ zdst,
    const float* __restrict__ W1, const float* __restrict__ b1,
    int nNodes, int nTiles)
{
    extern __shared__ float smem[];
    float* sW = smem;                                                // 64 KB
    unsigned long long* sZd = (unsigned long long*)(smem + HID*HID); // 64 KB

    const int nb   = gridDim.x >> 1;
    const int half = (blockIdx.x >= nb) ? 1 : 0;
    const int bid  = half ? (blockIdx.x - nb) : blockIdx.x;

    const float* z   = half ? zdst : zsrc;
    float*       out = half ? g_B  : g_A;
    const float* Wh  = W1 + half * HID * HID;

    const int tid = threadIdx.x;

    // Load W half into shared (once per CTA)
    for (int i = tid; i < HID * HID / 4; i += 256)
        ((float4*)sW)[i] = ((const float4*)Wh)[i];

    const int ng = tid & 15;    // node group
    const int cg = tid >> 4;    // col group (16 groups x 8 cols)

    unsigned long long binit[4];
    #pragma unroll
    for (int j = 0; j < 4; j++)
        binit[j] = half ? 0ULL : pack2(b1[cg*8 + 2*j], b1[cg*8 + 2*j + 1]);

    // Prefetch mapping: thread = (node nl, quarter q of the 128-float row)
    const int nl = tid >> 2;    // 0..63
    const int q  = tid & 3;     // 0..3

    float4 f[8];
    int t = bid;
    {
        int node = t * 64 + nl;
        if (t < nTiles && node < nNodes) {
            const float4* zr = (const float4*)(z + (size_t)node * HID) + q * 8;
            #pragma unroll
            for (int j = 0; j < 8; j++) f[j] = zr[j];
        } else {
            #pragma unroll
            for (int j = 0; j < 8; j++) f[j] = make_float4(0.f,0.f,0.f,0.f);
        }
    }

    for (; t < nTiles; t += nb) {
        __syncthreads();
        // Store current tile's z, duplicated, layout sZd[k*64 + node]
        #pragma unroll
        for (int j = 0; j < 8; j++) {
            int kb = q * 32 + j * 4;
            sZd[(kb + 0) * 64 + nl] = pack2(f[j].x, f[j].x);
            sZd[(kb + 1) * 64 + nl] = pack2(f[j].y, f[j].y);
            sZd[(kb + 2) * 64 + nl] = pack2(f[j].z, f[j].z);
            sZd[(kb + 3) * 64 + nl] = pack2(f[j].w, f[j].w);
        }
        __syncthreads();

        // Prefetch next tile (overlaps the mainloop below)
        int tn = t + nb;
        if (tn < nTiles) {
            int node = tn * 64 + nl;
            if (node < nNodes) {
                const float4* zr = (const float4*)(z + (size_t)node * HID) + q * 8;
                #pragma unroll
                for (int j = 0; j < 8; j++) f[j] = zr[j];
            } else {
                #pragma unroll
                for (int j = 0; j < 8; j++) f[j] = make_float4(0.f,0.f,0.f,0.f);
            }
        }

        unsigned long long acc[4][4];
        #pragma unroll
        for (int i = 0; i < 4; i++)
            #pragma unroll
            for (int j = 0; j < 4; j++) acc[i][j] = binit[j];

        #pragma unroll 8
        for (int k = 0; k < HID; k++) {
            unsigned long long wp[4];
            #pragma unroll
            for (int j = 0; j < 4; j++)      // adjacent cols -> free pairs
                wp[j] = *(const unsigned long long*)&sW[k*HID + cg*8 + 2*j];
            #pragma unroll
            for (int i = 0; i < 4; i++) {
                unsigned long long zp = sZd[k*64 + ng + 16*i]; // pre-dup'd
                #pragma unroll
                for (int j = 0; j < 4; j++)
                    acc[i][j] = fma2(zp, wp[j], acc[i][j]);
            }
        }

        #pragma unroll
        for (int i = 0; i < 4; i++) {
            int node = t * 64 + ng + 16 * i;
            if (node >= nNodes) continue;
            float2 p0 = unpack2(acc[i][0]);
            float2 p1 = unpack2(acc[i][1]);
            float2 p2 = unpack2(acc[i][2]);
            float2 p3 = unpack2(acc[i][3]);
            float4* op = (float4*)(out + (size_t)node * HID + cg * 8);
            op[0] = make_float4(p0.x, p0.y, p1.x, p1.y);
            op[1] = make_float4(p2.x, p2.y, p3.x, p3.y);
        }
    }
}

// ---------------------------------------------------------------------------
// Edge kernel: warp per 4 edges (unrolled) -> 8 independent LDG.128 in flight,
// 4 parallel shfl-reduction chains, uniform int4 index loads, float4 store.
// ---------------------------------------------------------------------------
__global__ __launch_bounds__(256) void edge_kernel(
    const float* __restrict__ W2, const float* __restrict__ b2,
    float* __restrict__ out, int E2)
{
    const int lane = threadIdx.x & 31;
    const int gw   = (blockIdx.x * blockDim.x + threadIdx.x) >> 5;
    const int nw   = (gridDim.x * blockDim.x) >> 5;

    const float4 w2v = ((const float4*)W2)[lane];
    const float  b2s = b2[0];
    const float4* A4 = (const float4*)g_A;
    const float4* B4 = (const float4*)g_B;

    const int E2r = E2 & ~3;

    for (int base = gw * 4; base < E2r; base += nw * 4) {
        int4 s4 = *(const int4*)&g_SIDX[base];
        int4 d4 = *(const int4*)&g_DIDX[base];

        float4 a0 = A4[(size_t)s4.x * 32 + lane];
        float4 b0 = B4[(size_t)d4.x * 32 + lane];
        float4 a1 = A4[(size_t)s4.y * 32 + lane];
        float4 b1 = B4[(size_t)d4.y * 32 + lane];
        float4 a2 = A4[(size_t)s4.z * 32 + lane];
        float4 b2v4 = B4[(size_t)d4.z * 32 + lane];
        float4 a3 = A4[(size_t)s4.w * 32 + lane];
        float4 b3 = B4[(size_t)d4.w * 32 + lane];

        float p0 = fmaxf(a0.x+b0.x,0.f)*w2v.x + fmaxf(a0.y+b0.y,0.f)*w2v.y
                 + fmaxf(a0.z+b0.z,0.f)*w2v.z + fmaxf(a0.w+b0.w,0.f)*w2v.w;
        float p1 = fmaxf(a1.x+b1.x,0.f)*w2v.x + fmaxf(a1.y+b1.y,0.f)*w2v.y
                 + fmaxf(a1.z+b1.z,0.f)*w2v.z + fmaxf(a1.w+b1.w,0.f)*w2v.w;
        float p2 = fmaxf(a2.x+b2v4.x,0.f)*w2v.x + fmaxf(a2.y+b2v4.y,0.f)*w2v.y
                 + fmaxf(a2.z+b2v4.z,0.f)*w2v.z + fmaxf(a2.w+b2v4.w,0.f)*w2v.w;
        float p3 = fmaxf(a3.x+b3.x,0.f)*w2v.x + fmaxf(a3.y+b3.y,0.f)*w2v.y
                 + fmaxf(a3.z+b3.z,0.f)*w2v.z + fmaxf(a3.w+b3.w,0.f)*w2v.w;

        #pragma unroll
        for (int off = 16; off; off >>= 1) {   // 4 independent chains
            p0 += __shfl_xor_sync(0xffffffffu, p0, off);
            p1 += __shfl_xor_sync(0xffffffffu, p1, off);
            p2 += __shfl_xor_sync(0xffffffffu, p2, off);
            p3 += __shfl_xor_sync(0xffffffffu, p3, off);
        }

        if (lane == 0)
            *(float4*)&out[base] = make_float4(p0+b2s, p1+b2s, p2+b2s, p3+b2s);
    }

    // Tail (E2 not divisible by 4): first warp handles it scalar.
    if (gw == 0) {
        for (int e = E2r; e < E2; e++) {
            size_t s = (size_t)g_SIDX[e];
            size_t d = (size_t)g_DIDX[e];
            float4 a = A4[s * 32 + lane];
            float4 b = B4[d * 32 + lane];
            float p = fmaxf(a.x+b.x,0.f)*w2v.x + fmaxf(a.y+b.y,0.f)*w2v.y
                    + fmaxf(a.z+b.z,0.f)*w2v.z + fmaxf(a.w+b.w,0.f)*w2v.w;
            #pragma unroll
            for (int off = 16; off; off >>= 1)
                p += __shfl_xor_sync(0xffffffffu, p, off);
            if (lane == 0) out[e] = p + b2s;
        }
    }
}

// ---------------------------------------------------------------------------
extern "C" void kernel_launch(void* const* d_in, const int* in_sizes, int n_in,
                              void* d_out, int out_size)
{
    // Resolve input ordering: dict order vs name-sorted order.
    const float *zsrc, *zdst, *W1, *b1, *W2, *b2;
    const void  *ps, *pd, *ns, *nd;
    int zElems, eElems;
    if (in_sizes[0] == 2 * HID * HID) {
        // name-sorted: W1, W2, b1, b2, neg_dst, neg_src, pos_dst, pos_src, z_dst, z_src
        W1 = (const float*)d_in[0];
        W2 = (const float*)d_in[1];
        b1 = (const float*)d_in[2];
        b2 = (const float*)d_in[3];
        nd = d_in[4]; ns = d_in[5];
        pd = d_in[6]; ps = d_in[7];
        zdst = (const float*)d_in[8];
        zsrc = (const float*)d_in[9];
        zElems = in_sizes[8];
        eElems = in_sizes[4];
    } else {
        // dict order: z_src, z_dst, pos_src, pos_dst, neg_src, neg_dst, W1, b1, W2, b2
        zsrc = (const float*)d_in[0];
        zdst = (const float*)d_in[1];
        ps = d_in[2]; pd = d_in[3];
        ns = d_in[4]; nd = d_in[5];
        W1 = (const float*)d_in[6];
        b1 = (const float*)d_in[7];
        W2 = (const float*)d_in[8];
        b2 = (const float*)d_in[9];
        zElems = in_sizes[0];
        eElems = in_sizes[2];
    }

    int nNodes = zElems / HID;
    if (nNodes > MAXN) nNodes = MAXN;
    const int E2 = out_size;   // 2E
    const int Eh = eElems;     // E
    const int nTiles = (nNodes + 63) / 64;

    const int smem = (HID * HID) * 4 + (HID * 64) * 8;   // 131072 B
    cudaFuncSetAttribute(precompute_kernel,
                         cudaFuncAttributeMaxDynamicSharedMemorySize, smem);

    convert_idx_kernel<<<(E2 + 255) / 256, 256>>>(ps, pd, ns, nd, E2, Eh, nNodes);

    int nb = 148;                       // persistent CTAs per half
    if (nb > nTiles) nb = nTiles;
    precompute_kernel<<<2 * nb, 256, smem>>>(zsrc, zdst, W1, b1, nNodes, nTiles);

    edge_kernel<<<8192, 256>>>(W2, b2, (float*)d_out, E2);
}